// round 1
// baseline (speedup 1.0000x reference)
#include <cuda_runtime.h>

#define B_ 2
#define S_ 2048
#define D_ 1024
#define H_ 16
#define DEPTH_ 64
#define SCALE_ 0.125f
#define NEG_ (-1.0e9f)

// Scratch (device globals — no allocations allowed)
__device__ float g_Qh[B_*H_*S_*DEPTH_];
__device__ float g_Kh[B_*H_*S_*DEPTH_];
__device__ float g_Vh[B_*H_*S_*DEPTH_];
__device__ float g_ctx[B_*S_*D_];
__device__ float g_rinv[B_*H_*S_];

// ---------------------------------------------------------------------------
// Tiled fp32 GEMM: C = A[4096,1024] @ W[1024,1024] + bias
// HEADED: store into [B,H,S,64] layout; else row-major [4096,1024].
// ---------------------------------------------------------------------------
template<bool HEADED>
__global__ __launch_bounds__(256)
void gemm_bias_kernel(const float* __restrict__ A, const float* __restrict__ W,
                      const float* __restrict__ bias, float* __restrict__ C)
{
    __shared__ float As[16][65];   // [kk][m]
    __shared__ float Bs[16][64];   // [kk][n]
    const int t  = threadIdx.x;
    const int m0 = blockIdx.y * 64;
    const int n0 = blockIdx.x * 64;
    const int ty = t >> 4, tx = t & 15;

    const int am = t >> 2;          // 0..63
    const int ak = (t & 3) * 4;     // 0,4,8,12
    const int bk = t >> 4;          // 0..15
    const int bn = (t & 15) * 4;    // 0..60

    float acc[4][4];
#pragma unroll
    for (int i = 0; i < 4; i++)
#pragma unroll
        for (int j = 0; j < 4; j++) acc[i][j] = 0.f;

    for (int k0 = 0; k0 < 1024; k0 += 16) {
        float4 av = *(const float4*)&A[(size_t)(m0 + am) * 1024 + k0 + ak];
        float4 bv = *(const float4*)&W[(size_t)(k0 + bk) * 1024 + n0 + bn];
        As[ak + 0][am] = av.x; As[ak + 1][am] = av.y;
        As[ak + 2][am] = av.z; As[ak + 3][am] = av.w;
        *(float4*)&Bs[bk][bn] = bv;
        __syncthreads();
#pragma unroll
        for (int kk = 0; kk < 16; kk++) {
            float a[4], b[4];
#pragma unroll
            for (int i = 0; i < 4; i++) a[i] = As[kk][ty + 16 * i];
#pragma unroll
            for (int j = 0; j < 4; j++) b[j] = Bs[kk][tx + 16 * j];
#pragma unroll
            for (int i = 0; i < 4; i++)
#pragma unroll
                for (int j = 0; j < 4; j++) acc[i][j] += a[i] * b[j];
        }
        __syncthreads();
    }

#pragma unroll
    for (int i = 0; i < 4; i++) {
#pragma unroll
        for (int j = 0; j < 4; j++) {
            const int m = m0 + ty + 16 * i;
            const int n = n0 + tx + 16 * j;
            const float val = acc[i][j] + bias[n];
            if (HEADED) {
                const int bb = m >> 11, s = m & 2047;
                const int h = n >> 6, dd = n & 63;
                C[(((size_t)(bb * H_ + h) << 11) + s) * DEPTH_ + dd] = val;
            } else {
                C[(size_t)m * 1024 + n] = val;
            }
        }
    }
}

// ---------------------------------------------------------------------------
// Attention: one block = (b,h, 16 query rows). Single pass, no max-subtract
// (logits are bounded; masked keys give expf(-1e9)=0 exactly).
// Writes unnormalized probs to attn output, ctx/rowsum to globals.
// ---------------------------------------------------------------------------
__global__ __launch_bounds__(256)
void attn_kernel(const float* __restrict__ mask, float* __restrict__ attn)
{
    __shared__ float Qs[16][64];
    __shared__ float Ks[64][65];
    __shared__ float Vs[64][68];
    __shared__ float Ps[16][68];
    __shared__ float Mt[64];
    __shared__ float rowsum[16];

    const int t  = threadIdx.x;
    const int bh = blockIdx.y;          // 0..31
    const int b  = bh >> 4;
    const int h  = bh & 15;
    const int q0 = blockIdx.x * 16;

    const float* __restrict__ Qbase = g_Qh + ((size_t)bh * S_ + q0) * DEPTH_;
    const float* __restrict__ Kbh   = g_Kh + (size_t)bh * S_ * DEPTH_;
    const float* __restrict__ Vbh   = g_Vh + (size_t)bh * S_ * DEPTH_;

    // load Q tile (16x64) vectorized
    {
        const int r = t >> 4, d4 = (t & 15) * 4;
        *(float4*)&Qs[r][d4] = *(const float4*)&Qbase[(size_t)r * DEPTH_ + d4];
    }
    if (t < 16) rowsum[t] = 0.f;

    // logits mapping: each thread -> 2 queries x 2 keys (strided keys c, c+32)
    const int c  = t & 31;
    const int qp = t >> 5;
    const int qA = 2 * qp, qB = 2 * qp + 1;
    // V-accum mapping: each thread -> 1 query (vq) x 4 dims (vd..vd+3)
    const int vq = t >> 4;
    const int vd = (t & 15) * 4;

    float4 ctx = make_float4(0.f, 0.f, 0.f, 0.f);
    float rsA = 0.f, rsB = 0.f;

    for (int kt = 0; kt < 32; kt++) {
        const int kb = kt * 64;
        // load K tile (64x64)
#pragma unroll
        for (int r = 0; r < 4; r++) {
            const int e = t + 256 * r;
            const int k = e >> 4, d4 = (e & 15) * 4;
            float4 kv = *(const float4*)&Kbh[(size_t)(kb + k) * DEPTH_ + d4];
            Ks[k][d4 + 0] = kv.x; Ks[k][d4 + 1] = kv.y;
            Ks[k][d4 + 2] = kv.z; Ks[k][d4 + 3] = kv.w;
        }
        if (t < 64) Mt[t] = mask[b * S_ + kb + t] * NEG_;
        __syncthreads();   // sync1: K/Mt ready; also gates Ps/Vs overwrite

        // logits for 2q x 2k
        float aAA = 0.f, aAB = 0.f, aBA = 0.f, aBB = 0.f;
#pragma unroll
        for (int d = 0; d < 64; d++) {
            const float ka = Ks[c][d];
            const float kb2 = Ks[c + 32][d];
            const float qa = Qs[qA][d];
            const float qb = Qs[qB][d];
            aAA += qa * ka; aAB += qa * kb2;
            aBA += qb * ka; aBB += qb * kb2;
        }
        const float pAA = __expf(aAA * SCALE_ + Mt[c]);
        const float pAB = __expf(aAB * SCALE_ + Mt[c + 32]);
        const float pBA = __expf(aBA * SCALE_ + Mt[c]);
        const float pBB = __expf(aBB * SCALE_ + Mt[c + 32]);

        Ps[qA][c] = pAA; Ps[qA][c + 32] = pAB;
        Ps[qB][c] = pBA; Ps[qB][c + 32] = pBB;

        const size_t obase = ((size_t)bh * S_ + q0 + qA) * S_ + kb;
        attn[obase + c]           = pAA;
        attn[obase + c + 32]      = pAB;
        attn[obase + S_ + c]      = pBA;
        attn[obase + S_ + c + 32] = pBB;

        rsA += pAA + pAB;
        rsB += pBA + pBB;

        // load V tile (64x64)
#pragma unroll
        for (int r = 0; r < 4; r++) {
            const int e = t + 256 * r;
            const int k = e >> 4, d4 = (e & 15) * 4;
            *(float4*)&Vs[k][d4] =
                *(const float4*)&Vbh[(size_t)(kb + k) * DEPTH_ + d4];
        }
        __syncthreads();   // sync2: Ps + Vs ready

        // ctx accumulation: ctx[vq][vd..vd+3] += sum_kk Ps[vq][kk]*Vs[kk][vd..]
#pragma unroll
        for (int kk = 0; kk < 64; kk += 4) {
            const float4 pv = *(const float4*)&Ps[vq][kk];
            const float4 v0 = *(const float4*)&Vs[kk + 0][vd];
            const float4 v1 = *(const float4*)&Vs[kk + 1][vd];
            const float4 v2 = *(const float4*)&Vs[kk + 2][vd];
            const float4 v3 = *(const float4*)&Vs[kk + 3][vd];
            ctx.x += pv.x * v0.x + pv.y * v1.x + pv.z * v2.x + pv.w * v3.x;
            ctx.y += pv.x * v0.y + pv.y * v1.y + pv.z * v2.y + pv.w * v3.y;
            ctx.z += pv.x * v0.z + pv.y * v1.z + pv.z * v2.z + pv.w * v3.z;
            ctx.w += pv.x * v0.w + pv.y * v1.w + pv.z * v2.w + pv.w * v3.w;
        }
        // no trailing sync needed: next iter's sync1 gates Ps/Vs reuse
    }

    atomicAdd(&rowsum[qA], rsA);
    atomicAdd(&rowsum[qB], rsB);
    __syncthreads();

    if (t < 16) g_rinv[(size_t)bh * S_ + q0 + t] = 1.0f / rowsum[t];

    const float ri = 1.0f / rowsum[vq];
    float4 o;
    o.x = ctx.x * ri; o.y = ctx.y * ri; o.z = ctx.z * ri; o.w = ctx.w * ri;
    // merged-head ctx layout [B,S,D]: ctx[b][q0+vq][h*64 + vd..]
    *(float4*)&g_ctx[((size_t)b * S_ + q0 + vq) * D_ + h * DEPTH_ + vd] = o;
}

// ---------------------------------------------------------------------------
// Normalize attn in place: attn[row][k] *= g_rinv[row]
// ---------------------------------------------------------------------------
__global__ __launch_bounds__(256)
void norm_attn_kernel(float* __restrict__ attn)
{
    const size_t i = (size_t)blockIdx.x * 256 + threadIdx.x;  // float4 index
    // total float4 = B*H*S*S/4 = 33554432; 512 float4 per row
    float4 v = ((float4*)attn)[i];
    const float r = g_rinv[i >> 9];
    v.x *= r; v.y *= r; v.z *= r; v.w *= r;
    ((float4*)attn)[i] = v;
}

// ---------------------------------------------------------------------------
extern "C" void kernel_launch(void* const* d_in, const int* in_sizes, int n_in,
                              void* d_out, int out_size)
{
    const float* q    = (const float*)d_in[0];
    const float* k    = (const float*)d_in[1];
    const float* v    = (const float*)d_in[2];
    const float* mask = (const float*)d_in[3];
    const float* wq   = (const float*)d_in[4];
    const float* bq   = (const float*)d_in[5];
    const float* wk   = (const float*)d_in[6];
    const float* bk   = (const float*)d_in[7];
    const float* wv   = (const float*)d_in[8];
    const float* bv   = (const float*)d_in[9];
    const float* wo   = (const float*)d_in[10];
    const float* bo   = (const float*)d_in[11];

    float* out  = (float*)d_out;                       // [B,S,D]
    float* attn = out + (size_t)B_ * S_ * D_;          // [B,H,S,S]

    float *pQh, *pKh, *pVh, *pCtx;
    cudaGetSymbolAddress((void**)&pQh,  g_Qh);
    cudaGetSymbolAddress((void**)&pKh,  g_Kh);
    cudaGetSymbolAddress((void**)&pVh,  g_Vh);
    cudaGetSymbolAddress((void**)&pCtx, g_ctx);

    const dim3 ggrid(16, 64);   // N/64, M/64
    gemm_bias_kernel<true><<<ggrid, 256>>>(q, wq, bq, pQh);
    gemm_bias_kernel<true><<<ggrid, 256>>>(k, wk, bk, pKh);
    gemm_bias_kernel<true><<<ggrid, 256>>>(v, wv, bv, pVh);

    attn_kernel<<<dim3(S_ / 16, B_ * H_), 256>>>(mask, attn);

    norm_attn_kernel<<<(B_ * H_ * (size_t)S_ * S_ / 4) / 256, 256>>>(attn);

    gemm_bias_kernel<false><<<ggrid, 256>>>(pCtx, wo, bo, out);
}

// round 2
// speedup vs baseline: 1.2804x; 1.2804x over previous
#include <cuda_runtime.h>

#define B_ 2
#define S_ 2048
#define D_ 1024
#define H_ 16
#define DEPTH_ 64
#define SCALE_ 0.125f
#define NEG_ (-1.0e9f)

// Scratch (device globals — no allocations allowed)
__device__ float g_Qh[B_*H_*S_*DEPTH_];
__device__ float g_Kh[B_*H_*S_*DEPTH_];
__device__ float g_Vh[B_*H_*S_*DEPTH_];
__device__ float g_ctx[B_*S_*D_];
__device__ float g_rinv[B_*H_*S_];

__device__ __forceinline__ unsigned f2tf32(float f) {
    unsigned u; asm("cvt.rna.tf32.f32 %0, %1;" : "=r"(u) : "f"(f)); return u;
}

#define MMA_TF32(d, a, b)                                                     \
    asm volatile(                                                             \
        "mma.sync.aligned.m16n8k8.row.col.f32.tf32.tf32.f32 "                 \
        "{%0,%1,%2,%3},{%4,%5,%6,%7},{%8,%9},{%0,%1,%2,%3};"                  \
        : "+f"(d[0]), "+f"(d[1]), "+f"(d[2]), "+f"(d[3])                      \
        : "r"(a[0]), "r"(a[1]), "r"(a[2]), "r"(a[3]), "r"(b[0]), "r"(b[1]))

// ---------------------------------------------------------------------------
// tf32 tensor-core GEMM: C = A[4096,1024] @ W[1024,1024] + bias
// CTA tile 128x128, BK=16, 8 warps (4x2), warp tile 32x64 (2x8 mma tiles).
// HEADED: store into [B,H,S,64] layout; else row-major.
// QKV: if z-batched, pointers selected by blockIdx.z.
// ---------------------------------------------------------------------------
template<bool HEADED, bool ZSEL>
__global__ __launch_bounds__(256)
void gemm_tf32_kernel(const float* __restrict__ A0, const float* __restrict__ W0,
                      const float* __restrict__ bias0, float* __restrict__ C0,
                      const float* A1, const float* W1, const float* bias1, float* C1,
                      const float* A2, const float* W2, const float* bias2, float* C2)
{
    __shared__ unsigned As[128][20];   // [m][k], stride 20 -> conflict-free frags
    __shared__ unsigned Bs[16][132];   // [k][n], stride 132 -> conflict-free frags

    const float* A = A0; const float* W = W0; const float* bias = bias0; float* C = C0;
    if (ZSEL) {
        if (blockIdx.z == 1) { A = A1; W = W1; bias = bias1; C = C1; }
        else if (blockIdx.z == 2) { A = A2; W = W2; bias = bias2; C = C2; }
    }

    const int t    = threadIdx.x;
    const int m0   = blockIdx.y * 128;
    const int n0   = blockIdx.x * 128;
    const int lane = t & 31, warp = t >> 5;
    const int wm   = warp >> 1, wn = warp & 1;     // 4 x 2 warp grid
    const int gid  = lane >> 2, tid4 = lane & 3;

    // gmem staging mapping
    const int ar = t >> 1,  ac = (t & 1) * 8;      // A: 128 rows x 16 cols
    const int br = t >> 4,  bc = (t & 15) * 8;     // B: 16 rows x 128 cols

    const float* Aptr = A + (size_t)(m0 + ar) * 1024 + ac;
    const float* Wptr = W + (size_t)br * 1024 + n0 + bc;

    float acc[2][8][4];
#pragma unroll
    for (int i = 0; i < 2; i++)
#pragma unroll
        for (int j = 0; j < 8; j++)
#pragma unroll
            for (int c = 0; c < 4; c++) acc[i][j][c] = 0.f;

    // prologue: stage tile 0
    float4 av0 = *(const float4*)(Aptr);
    float4 av1 = *(const float4*)(Aptr + 4);
    float4 bv0 = *(const float4*)(Wptr);
    float4 bv1 = *(const float4*)(Wptr + 4);

    for (int kt = 0; kt < 64; kt++) {
        // commit staged tile to smem (tf32-rounded)
        As[ar][ac + 0] = f2tf32(av0.x); As[ar][ac + 1] = f2tf32(av0.y);
        As[ar][ac + 2] = f2tf32(av0.z); As[ar][ac + 3] = f2tf32(av0.w);
        As[ar][ac + 4] = f2tf32(av1.x); As[ar][ac + 5] = f2tf32(av1.y);
        As[ar][ac + 6] = f2tf32(av1.z); As[ar][ac + 7] = f2tf32(av1.w);
        Bs[br][bc + 0] = f2tf32(bv0.x); Bs[br][bc + 1] = f2tf32(bv0.y);
        Bs[br][bc + 2] = f2tf32(bv0.z); Bs[br][bc + 3] = f2tf32(bv0.w);
        Bs[br][bc + 4] = f2tf32(bv1.x); Bs[br][bc + 5] = f2tf32(bv1.y);
        Bs[br][bc + 6] = f2tf32(bv1.z); Bs[br][bc + 7] = f2tf32(bv1.w);
        __syncthreads();

        // stage next tile (overlaps with MMA below)
        if (kt < 63) {
            const int ko = (kt + 1) * 16;
            av0 = *(const float4*)(Aptr + ko);
            av1 = *(const float4*)(Aptr + ko + 4);
            bv0 = *(const float4*)(Wptr + (size_t)ko * 1024);
            bv1 = *(const float4*)(Wptr + (size_t)ko * 1024 + 4);
        }

        // compute: 2 k8 steps x (2 m-tiles x 8 n-tiles) mma
#pragma unroll
        for (int s = 0; s < 2; s++) {
            unsigned af[2][4], bf[8][2];
#pragma unroll
            for (int i = 0; i < 2; i++) {
                const int r = wm * 32 + i * 16 + gid;
                const int kc = 8 * s + tid4;
                af[i][0] = As[r][kc];     af[i][1] = As[r + 8][kc];
                af[i][2] = As[r][kc + 4]; af[i][3] = As[r + 8][kc + 4];
            }
#pragma unroll
            for (int j = 0; j < 8; j++) {
                const int cn = wn * 64 + j * 8 + gid;
                bf[j][0] = Bs[8 * s + tid4][cn];
                bf[j][1] = Bs[8 * s + 4 + tid4][cn];
            }
#pragma unroll
            for (int i = 0; i < 2; i++)
#pragma unroll
                for (int j = 0; j < 8; j++) MMA_TF32(acc[i][j], af[i], bf[j]);
        }
        __syncthreads();
    }

    // epilogue: bias + store
#pragma unroll
    for (int i = 0; i < 2; i++) {
#pragma unroll
        for (int j = 0; j < 8; j++) {
            const int n = n0 + wn * 64 + j * 8 + tid4 * 2;
            const float b0 = bias[n], b1 = bias[n + 1];
#pragma unroll
            for (int half = 0; half < 2; half++) {
                const int m = m0 + wm * 32 + i * 16 + gid + half * 8;
                const float v0 = acc[i][j][half * 2 + 0] + b0;
                const float v1 = acc[i][j][half * 2 + 1] + b1;
                if (HEADED) {
                    const int bb = m >> 11, s = m & 2047;
                    const int h = n >> 6, dd = n & 63;
                    float* dst = &C[(((size_t)(bb * H_ + h) << 11) + s) * DEPTH_ + dd];
                    dst[0] = v0; dst[1] = v1;
                } else {
                    C[(size_t)m * 1024 + n]     = v0;
                    C[(size_t)m * 1024 + n + 1] = v1;
                }
            }
        }
    }
}

// ---------------------------------------------------------------------------
// Attention: one block = (b,h, 16 query rows). Single pass, no max-subtract
// (logits bounded; masked keys give expf(-1e9)=0 exactly).
// ---------------------------------------------------------------------------
__global__ __launch_bounds__(256)
void attn_kernel(const float* __restrict__ mask, float* __restrict__ attn)
{
    __shared__ float Qs[16][64];
    __shared__ float Ks[64][65];
    __shared__ float Vs[64][68];
    __shared__ float Ps[16][68];
    __shared__ float Mt[64];
    __shared__ float rowsum[16];

    const int t  = threadIdx.x;
    const int bh = blockIdx.y;
    const int b  = bh >> 4;
    const int h  = bh & 15;
    const int q0 = blockIdx.x * 16;

    const float* __restrict__ Qbase = g_Qh + ((size_t)bh * S_ + q0) * DEPTH_;
    const float* __restrict__ Kbh   = g_Kh + (size_t)bh * S_ * DEPTH_;
    const float* __restrict__ Vbh   = g_Vh + (size_t)bh * S_ * DEPTH_;

    {
        const int r = t >> 4, d4 = (t & 15) * 4;
        *(float4*)&Qs[r][d4] = *(const float4*)&Qbase[(size_t)r * DEPTH_ + d4];
    }
    if (t < 16) rowsum[t] = 0.f;

    const int c  = t & 31;
    const int qp = t >> 5;
    const int qA = 2 * qp, qB = 2 * qp + 1;
    const int vq = t >> 4;
    const int vd = (t & 15) * 4;

    float4 ctx = make_float4(0.f, 0.f, 0.f, 0.f);
    float rsA = 0.f, rsB = 0.f;

    for (int kt = 0; kt < 32; kt++) {
        const int kb = kt * 64;
#pragma unroll
        for (int r = 0; r < 4; r++) {
            const int e = t + 256 * r;
            const int k = e >> 4, d4 = (e & 15) * 4;
            float4 kv = *(const float4*)&Kbh[(size_t)(kb + k) * DEPTH_ + d4];
            Ks[k][d4 + 0] = kv.x; Ks[k][d4 + 1] = kv.y;
            Ks[k][d4 + 2] = kv.z; Ks[k][d4 + 3] = kv.w;
        }
        if (t < 64) Mt[t] = mask[b * S_ + kb + t] * NEG_;
        __syncthreads();

        float aAA = 0.f, aAB = 0.f, aBA = 0.f, aBB = 0.f;
#pragma unroll
        for (int d = 0; d < 64; d++) {
            const float ka  = Ks[c][d];
            const float kb2 = Ks[c + 32][d];
            const float qa  = Qs[qA][d];
            const float qb  = Qs[qB][d];
            aAA += qa * ka; aAB += qa * kb2;
            aBA += qb * ka; aBB += qb * kb2;
        }
        const float pAA = __expf(aAA * SCALE_ + Mt[c]);
        const float pAB = __expf(aAB * SCALE_ + Mt[c + 32]);
        const float pBA = __expf(aBA * SCALE_ + Mt[c]);
        const float pBB = __expf(aBB * SCALE_ + Mt[c + 32]);

        Ps[qA][c] = pAA; Ps[qA][c + 32] = pAB;
        Ps[qB][c] = pBA; Ps[qB][c + 32] = pBB;

        const size_t obase = ((size_t)bh * S_ + q0 + qA) * S_ + kb;
        attn[obase + c]           = pAA;
        attn[obase + c + 32]      = pAB;
        attn[obase + S_ + c]      = pBA;
        attn[obase + S_ + c + 32] = pBB;

        rsA += pAA + pAB;
        rsB += pBA + pBB;

#pragma unroll
        for (int r = 0; r < 4; r++) {
            const int e = t + 256 * r;
            const int k = e >> 4, d4 = (e & 15) * 4;
            *(float4*)&Vs[k][d4] =
                *(const float4*)&Vbh[(size_t)(kb + k) * DEPTH_ + d4];
        }
        __syncthreads();

#pragma unroll
        for (int kk = 0; kk < 64; kk += 4) {
            const float4 pv = *(const float4*)&Ps[vq][kk];
            const float4 v0 = *(const float4*)&Vs[kk + 0][vd];
            const float4 v1 = *(const float4*)&Vs[kk + 1][vd];
            const float4 v2 = *(const float4*)&Vs[kk + 2][vd];
            const float4 v3 = *(const float4*)&Vs[kk + 3][vd];
            ctx.x += pv.x * v0.x + pv.y * v1.x + pv.z * v2.x + pv.w * v3.x;
            ctx.y += pv.x * v0.y + pv.y * v1.y + pv.z * v2.y + pv.w * v3.y;
            ctx.z += pv.x * v0.z + pv.y * v1.z + pv.z * v2.z + pv.w * v3.z;
            ctx.w += pv.x * v0.w + pv.y * v1.w + pv.z * v2.w + pv.w * v3.w;
        }
    }

    atomicAdd(&rowsum[qA], rsA);
    atomicAdd(&rowsum[qB], rsB);
    __syncthreads();

    if (t < 16) g_rinv[(size_t)bh * S_ + q0 + t] = 1.0f / rowsum[t];

    const float ri = 1.0f / rowsum[vq];
    float4 o;
    o.x = ctx.x * ri; o.y = ctx.y * ri; o.z = ctx.z * ri; o.w = ctx.w * ri;
    *(float4*)&g_ctx[((size_t)b * S_ + q0 + vq) * D_ + h * DEPTH_ + vd] = o;
}

// ---------------------------------------------------------------------------
__global__ __launch_bounds__(256)
void norm_attn_kernel(float* __restrict__ attn)
{
    const size_t i = (size_t)blockIdx.x * 256 + threadIdx.x;
    float4 v = ((float4*)attn)[i];
    const float r = g_rinv[i >> 9];
    v.x *= r; v.y *= r; v.z *= r; v.w *= r;
    ((float4*)attn)[i] = v;
}

// ---------------------------------------------------------------------------
extern "C" void kernel_launch(void* const* d_in, const int* in_sizes, int n_in,
                              void* d_out, int out_size)
{
    const float* q    = (const float*)d_in[0];
    const float* k    = (const float*)d_in[1];
    const float* v    = (const float*)d_in[2];
    const float* mask = (const float*)d_in[3];
    const float* wq   = (const float*)d_in[4];
    const float* bq   = (const float*)d_in[5];
    const float* wk   = (const float*)d_in[6];
    const float* bk   = (const float*)d_in[7];
    const float* wv   = (const float*)d_in[8];
    const float* bv   = (const float*)d_in[9];
    const float* wo   = (const float*)d_in[10];
    const float* bo   = (const float*)d_in[11];

    float* out  = (float*)d_out;
    float* attn = out + (size_t)B_ * S_ * D_;

    float *pQh, *pKh, *pVh, *pCtx;
    cudaGetSymbolAddress((void**)&pQh,  g_Qh);
    cudaGetSymbolAddress((void**)&pKh,  g_Kh);
    cudaGetSymbolAddress((void**)&pVh,  g_Vh);
    cudaGetSymbolAddress((void**)&pCtx, g_ctx);

    // fused QKV projections (z-batched), tf32 tensor cores
    gemm_tf32_kernel<true, true><<<dim3(8, 32, 3), 256>>>(
        q, wq, bq, pQh,
        k, wk, bk, pKh,
        v, wv, bv, pVh);

    attn_kernel<<<dim3(S_ / 16, B_ * H_), 256>>>(mask, attn);

    norm_attn_kernel<<<(B_ * H_ * (size_t)S_ * S_ / 4) / 256, 256>>>(attn);

    gemm_tf32_kernel<false, false><<<dim3(8, 32, 1), 256>>>(
        pCtx, wo, bo, out,
        nullptr, nullptr, nullptr, nullptr,
        nullptr, nullptr, nullptr, nullptr);
}

// round 3
// speedup vs baseline: 3.3781x; 2.6383x over previous
#include <cuda_runtime.h>

#define B_ 2
#define S_ 2048
#define D_ 1024
#define H_ 16
#define DEPTH_ 64
#define SCALE_ 0.125f
#define NEG_ (-1.0e9f)

// Scratch (device globals — no allocations allowed)
__device__ float g_Qh[B_*H_*S_*DEPTH_];
__device__ float g_Kh[B_*H_*S_*DEPTH_];
__device__ float g_Vh[B_*H_*S_*DEPTH_];
__device__ float g_ctx[B_*S_*D_];
__device__ float g_rinv[B_*H_*S_];

__device__ __forceinline__ unsigned f2tf32(float f) {
    unsigned u; asm("cvt.rna.tf32.f32 %0, %1;" : "=r"(u) : "f"(f)); return u;
}

#define MMA_TF32(d, a, b)                                                     \
    asm volatile(                                                             \
        "mma.sync.aligned.m16n8k8.row.col.f32.tf32.tf32.f32 "                 \
        "{%0,%1,%2,%3},{%4,%5,%6,%7},{%8,%9},{%0,%1,%2,%3};"                  \
        : "+f"(d[0]), "+f"(d[1]), "+f"(d[2]), "+f"(d[3])                      \
        : "r"(a[0]), "r"(a[1]), "r"(a[2]), "r"(a[3]), "r"(b[0]), "r"(b[1]))

// ---------------------------------------------------------------------------
// tf32 tensor-core GEMM: C = A[4096,1024] @ W[1024,1024] + bias  (unchanged)
// ---------------------------------------------------------------------------
template<bool HEADED, bool ZSEL>
__global__ __launch_bounds__(256)
void gemm_tf32_kernel(const float* __restrict__ A0, const float* __restrict__ W0,
                      const float* __restrict__ bias0, float* __restrict__ C0,
                      const float* A1, const float* W1, const float* bias1, float* C1,
                      const float* A2, const float* W2, const float* bias2, float* C2)
{
    __shared__ unsigned As[128][20];
    __shared__ unsigned Bs[16][132];

    const float* A = A0; const float* W = W0; const float* bias = bias0; float* C = C0;
    if (ZSEL) {
        if (blockIdx.z == 1) { A = A1; W = W1; bias = bias1; C = C1; }
        else if (blockIdx.z == 2) { A = A2; W = W2; bias = bias2; C = C2; }
    }

    const int t    = threadIdx.x;
    const int m0   = blockIdx.y * 128;
    const int n0   = blockIdx.x * 128;
    const int lane = t & 31, warp = t >> 5;
    const int wm   = warp >> 1, wn = warp & 1;
    const int gid  = lane >> 2, tid4 = lane & 3;

    const int ar = t >> 1,  ac = (t & 1) * 8;
    const int br = t >> 4,  bc = (t & 15) * 8;

    const float* Aptr = A + (size_t)(m0 + ar) * 1024 + ac;
    const float* Wptr = W + (size_t)br * 1024 + n0 + bc;

    float acc[2][8][4];
#pragma unroll
    for (int i = 0; i < 2; i++)
#pragma unroll
        for (int j = 0; j < 8; j++)
#pragma unroll
            for (int c = 0; c < 4; c++) acc[i][j][c] = 0.f;

    float4 av0 = *(const float4*)(Aptr);
    float4 av1 = *(const float4*)(Aptr + 4);
    float4 bv0 = *(const float4*)(Wptr);
    float4 bv1 = *(const float4*)(Wptr + 4);

    for (int kt = 0; kt < 64; kt++) {
        As[ar][ac + 0] = f2tf32(av0.x); As[ar][ac + 1] = f2tf32(av0.y);
        As[ar][ac + 2] = f2tf32(av0.z); As[ar][ac + 3] = f2tf32(av0.w);
        As[ar][ac + 4] = f2tf32(av1.x); As[ar][ac + 5] = f2tf32(av1.y);
        As[ar][ac + 6] = f2tf32(av1.z); As[ar][ac + 7] = f2tf32(av1.w);
        Bs[br][bc + 0] = f2tf32(bv0.x); Bs[br][bc + 1] = f2tf32(bv0.y);
        Bs[br][bc + 2] = f2tf32(bv0.z); Bs[br][bc + 3] = f2tf32(bv0.w);
        Bs[br][bc + 4] = f2tf32(bv1.x); Bs[br][bc + 5] = f2tf32(bv1.y);
        Bs[br][bc + 6] = f2tf32(bv1.z); Bs[br][bc + 7] = f2tf32(bv1.w);
        __syncthreads();

        if (kt < 63) {
            const int ko = (kt + 1) * 16;
            av0 = *(const float4*)(Aptr + ko);
            av1 = *(const float4*)(Aptr + ko + 4);
            bv0 = *(const float4*)(Wptr + (size_t)ko * 1024);
            bv1 = *(const float4*)(Wptr + (size_t)ko * 1024 + 4);
        }

#pragma unroll
        for (int s = 0; s < 2; s++) {
            unsigned af[2][4], bf[8][2];
#pragma unroll
            for (int i = 0; i < 2; i++) {
                const int r = wm * 32 + i * 16 + gid;
                const int kc = 8 * s + tid4;
                af[i][0] = As[r][kc];     af[i][1] = As[r + 8][kc];
                af[i][2] = As[r][kc + 4]; af[i][3] = As[r + 8][kc + 4];
            }
#pragma unroll
            for (int j = 0; j < 8; j++) {
                const int cn = wn * 64 + j * 8 + gid;
                bf[j][0] = Bs[8 * s + tid4][cn];
                bf[j][1] = Bs[8 * s + 4 + tid4][cn];
            }
#pragma unroll
            for (int i = 0; i < 2; i++)
#pragma unroll
                for (int j = 0; j < 8; j++) MMA_TF32(acc[i][j], af[i], bf[j]);
        }
        __syncthreads();
    }

#pragma unroll
    for (int i = 0; i < 2; i++) {
#pragma unroll
        for (int j = 0; j < 8; j++) {
            const int n = n0 + wn * 64 + j * 8 + tid4 * 2;
            const float b0 = bias[n], b1 = bias[n + 1];
#pragma unroll
            for (int half = 0; half < 2; half++) {
                const int m = m0 + wm * 32 + i * 16 + gid + half * 8;
                const float v0 = acc[i][j][half * 2 + 0] + b0;
                const float v1 = acc[i][j][half * 2 + 1] + b1;
                if (HEADED) {
                    const int bb = m >> 11, s = m & 2047;
                    const int h = n >> 6, dd = n & 63;
                    float* dst = &C[(((size_t)(bb * H_ + h) << 11) + s) * DEPTH_ + dd];
                    dst[0] = v0; dst[1] = v1;
                } else {
                    C[(size_t)m * 1024 + n]     = v0;
                    C[(size_t)m * 1024 + n + 1] = v1;
                }
            }
        }
    }
}

// ---------------------------------------------------------------------------
// MMA attention. One CTA = (b,h) x 64 queries. Computes S^T = K @ Q^T so both
// K (for S^T) and V (for P@V) use natural [key][d] smem layout (no transposes).
// Q^T B-fragments are loop-invariant registers. P roundtrips through smem
// (layout fix C-frag -> A-frag) and is stored coalesced to the attn output.
// Single pass, no max-subtract (logits bounded; expf(-1e9)=0).
// ---------------------------------------------------------------------------
#define KS(r, c) Ks[(r) * 68 + (c)]
#define VS(r, c) Vs[(r) * 68 + (c)]
#define PS(r, c) Ps[(r) * 68 + (c)]
#define ATTN_SMEM_BYTES ((3 * 64 * 68 + 128) * 4)

__global__ __launch_bounds__(256)
void attn_mma_kernel(const float* __restrict__ mask, float* __restrict__ attn)
{
    extern __shared__ char smem_raw[];
    unsigned* Ks = (unsigned*)smem_raw;            // [64][68] tf32 K  [key][d]
    unsigned* Vs = Ks + 64 * 68;                   // [64][68] tf32 V  [key][d]
    float*    Ps = (float*)(Vs + 64 * 68);         // [64][68] fp32 P  [q][key]
    float*    Mt = Ps + 64 * 68;                   // [64] mask*NEG
    float*    rowsum = Mt + 64;                    // [64]

    const int t    = threadIdx.x;
    const int bh   = blockIdx.y;
    const int b    = bh >> 4, h = bh & 15;
    const int q0   = blockIdx.x * 64;
    const int lane = t & 31, warp = t >> 5;
    const int gid  = lane >> 2, t4 = lane & 3;

    // S^T phase: wmS over keys (2x32), wnS over q (4x16)
    const int wmS = warp >> 2, wnS = warp & 3;
    // PV phase: wq over q (2x32), wd over d (4x16)
    const int wq = warp >> 2, wd = warp & 3;

    const float* __restrict__ Qbh = g_Qh + (size_t)bh * S_ * DEPTH_;
    const float* __restrict__ Kbh = g_Kh + (size_t)bh * S_ * DEPTH_;
    const float* __restrict__ Vbh = g_Vh + (size_t)bh * S_ * DEPTH_;

    // loop-invariant Q^T B-fragments: qb[j][s] covers q cols wnS*16+j*8+gid
    unsigned qb[2][8][2];
#pragma unroll
    for (int j = 0; j < 2; j++) {
        const int qn = q0 + wnS * 16 + j * 8 + gid;
        const float* Qrow = Qbh + (size_t)qn * DEPTH_;
#pragma unroll
        for (int s = 0; s < 8; s++) {
            qb[j][s][0] = f2tf32(Qrow[8 * s + t4]);
            qb[j][s][1] = f2tf32(Qrow[8 * s + t4 + 4]);
        }
    }

    if (t < 64) rowsum[t] = 0.f;

    float Oa[2][2][4];
#pragma unroll
    for (int i = 0; i < 2; i++)
#pragma unroll
        for (int j = 0; j < 2; j++)
#pragma unroll
            for (int c = 0; c < 4; c++) Oa[i][j][c] = 0.f;
    float ps_part[2][2] = {{0.f, 0.f}, {0.f, 0.f}};

    // tile-load mapping: thread t, r=0..3 -> f4 idx = t+256r: key=idx>>4, d4=(idx&15)*4
    float4 kreg[4], vreg[4];
#pragma unroll
    for (int r = 0; r < 4; r++) {
        const int idx = t + 256 * r, key = idx >> 4, d4 = (idx & 15) * 4;
        kreg[r] = *(const float4*)&Kbh[(size_t)key * DEPTH_ + d4];
        vreg[r] = *(const float4*)&Vbh[(size_t)key * DEPTH_ + d4];
    }

    for (int kt = 0; kt < 32; kt++) {
        const int kb = kt * 64;
        __syncthreads();   // prior consumers of Ks/Vs done

        // commit prefetched K/V tiles (tf32-converted)
#pragma unroll
        for (int r = 0; r < 4; r++) {
            const int idx = t + 256 * r, key = idx >> 4, d4 = (idx & 15) * 4;
            uint4 ku, vu;
            ku.x = f2tf32(kreg[r].x); ku.y = f2tf32(kreg[r].y);
            ku.z = f2tf32(kreg[r].z); ku.w = f2tf32(kreg[r].w);
            vu.x = f2tf32(vreg[r].x); vu.y = f2tf32(vreg[r].y);
            vu.z = f2tf32(vreg[r].z); vu.w = f2tf32(vreg[r].w);
            *(uint4*)&KS(key, d4) = ku;
            *(uint4*)&VS(key, d4) = vu;
        }
        if (t < 64) Mt[t] = mask[b * S_ + kb + t] * NEG_;
        __syncthreads();   // Ks/Vs/Mt ready

        // S^T = K @ Q^T : frag rows = keys, cols = q
        float sc[2][2][4];
#pragma unroll
        for (int i = 0; i < 2; i++)
#pragma unroll
            for (int j = 0; j < 2; j++)
#pragma unroll
                for (int c = 0; c < 4; c++) sc[i][j][c] = 0.f;

#pragma unroll
        for (int s = 0; s < 8; s++) {
            unsigned af[2][4];
#pragma unroll
            for (int i = 0; i < 2; i++) {
                const int r = wmS * 32 + i * 16 + gid;
                const int kc = 8 * s + t4;
                af[i][0] = KS(r, kc);     af[i][1] = KS(r + 8, kc);
                af[i][2] = KS(r, kc + 4); af[i][3] = KS(r + 8, kc + 4);
            }
#pragma unroll
            for (int i = 0; i < 2; i++)
#pragma unroll
                for (int j = 0; j < 2; j++) MMA_TF32(sc[i][j], af[i], qb[j][s]);
        }

        // exp + write P^T frags into Ps[q][key] (index swap = free transpose)
#pragma unroll
        for (int i = 0; i < 2; i++) {
            const int kr = wmS * 32 + i * 16 + gid;
            const float m0 = Mt[kr], m1 = Mt[kr + 8];
#pragma unroll
            for (int j = 0; j < 2; j++) {
                const int qc = wnS * 16 + j * 8 + 2 * t4;
                const float p0 = __expf(sc[i][j][0] * SCALE_ + m0);
                const float p1 = __expf(sc[i][j][1] * SCALE_ + m0);
                const float p2 = __expf(sc[i][j][2] * SCALE_ + m1);
                const float p3 = __expf(sc[i][j][3] * SCALE_ + m1);
                PS(qc, kr)         = p0;
                PS(qc + 1, kr)     = p1;
                PS(qc, kr + 8)     = p2;
                PS(qc + 1, kr + 8) = p3;
                ps_part[j][0] += p0 + p2;
                ps_part[j][1] += p1 + p3;
            }
        }
        __syncthreads();   // Ps complete

        // coalesced store of the unnormalized 64x64 P tile to attn
#pragma unroll
        for (int r = 0; r < 4; r++) {
            const int idx = t + 256 * r, ql = idx >> 4, k4 = (idx & 15) * 4;
            const float4 pv = *(const float4*)&PS(ql, k4);
            *(float4*)&attn[((size_t)(bh * S_ + q0 + ql)) * S_ + kb + k4] = pv;
        }

        // prefetch next tile (overlaps PV MMAs)
        if (kt < 31) {
            const int kb2 = kb + 64;
#pragma unroll
            for (int r = 0; r < 4; r++) {
                const int idx = t + 256 * r, key = idx >> 4, d4 = (idx & 15) * 4;
                kreg[r] = *(const float4*)&Kbh[(size_t)(kb2 + key) * DEPTH_ + d4];
                vreg[r] = *(const float4*)&Vbh[(size_t)(kb2 + key) * DEPTH_ + d4];
            }
        }

        // O += P @ V
#pragma unroll
        for (int s = 0; s < 8; s++) {
            unsigned af[2][4], bf[2][2];
#pragma unroll
            for (int i = 0; i < 2; i++) {
                const int qr = wq * 32 + i * 16 + gid;
                const int kc = 8 * s + t4;
                af[i][0] = f2tf32(PS(qr, kc));     af[i][1] = f2tf32(PS(qr + 8, kc));
                af[i][2] = f2tf32(PS(qr, kc + 4)); af[i][3] = f2tf32(PS(qr + 8, kc + 4));
            }
#pragma unroll
            for (int j = 0; j < 2; j++) {
                const int dn = wd * 16 + j * 8 + gid;
                bf[j][0] = VS(8 * s + t4, dn);
                bf[j][1] = VS(8 * s + 4 + t4, dn);
            }
#pragma unroll
            for (int i = 0; i < 2; i++)
#pragma unroll
                for (int j = 0; j < 2; j++) MMA_TF32(Oa[i][j], af[i], bf[j]);
        }
    }

    // rowsum: reduce over gid lanes (keys), then across the 2 wmS warps
#pragma unroll
    for (int j = 0; j < 2; j++)
#pragma unroll
        for (int c = 0; c < 2; c++) {
            float v = ps_part[j][c];
            v += __shfl_xor_sync(0xffffffffu, v, 4);
            v += __shfl_xor_sync(0xffffffffu, v, 8);
            v += __shfl_xor_sync(0xffffffffu, v, 16);
            ps_part[j][c] = v;
        }
    if (gid == 0) {
#pragma unroll
        for (int j = 0; j < 2; j++)
#pragma unroll
            for (int c = 0; c < 2; c++)
                atomicAdd(&rowsum[wnS * 16 + j * 8 + 2 * t4 + c], ps_part[j][c]);
    }
    __syncthreads();

    if (t < 64) g_rinv[(size_t)bh * S_ + q0 + t] = 1.0f / rowsum[t];

    // normalized context out
#pragma unroll
    for (int i = 0; i < 2; i++) {
        const int qr = wq * 32 + i * 16 + gid;
        const float r0 = 1.0f / rowsum[qr];
        const float r1 = 1.0f / rowsum[qr + 8];
#pragma unroll
        for (int j = 0; j < 2; j++) {
            const int dn = wd * 16 + j * 8 + 2 * t4;
            float* dst0 = &g_ctx[((size_t)(b * S_ + q0 + qr)) * D_ + h * DEPTH_ + dn];
            float* dst1 = &g_ctx[((size_t)(b * S_ + q0 + qr + 8)) * D_ + h * DEPTH_ + dn];
            dst0[0] = Oa[i][j][0] * r0; dst0[1] = Oa[i][j][1] * r0;
            dst1[0] = Oa[i][j][2] * r1; dst1[1] = Oa[i][j][3] * r1;
        }
    }
}

// ---------------------------------------------------------------------------
__global__ __launch_bounds__(256)
void norm_attn_kernel(float* __restrict__ attn)
{
    const size_t i = (size_t)blockIdx.x * 256 + threadIdx.x;
    float4 v = ((float4*)attn)[i];
    const float r = g_rinv[i >> 9];
    v.x *= r; v.y *= r; v.z *= r; v.w *= r;
    ((float4*)attn)[i] = v;
}

// ---------------------------------------------------------------------------
extern "C" void kernel_launch(void* const* d_in, const int* in_sizes, int n_in,
                              void* d_out, int out_size)
{
    const float* q    = (const float*)d_in[0];
    const float* k    = (const float*)d_in[1];
    const float* v    = (const float*)d_in[2];
    const float* mask = (const float*)d_in[3];
    const float* wq   = (const float*)d_in[4];
    const float* bq   = (const float*)d_in[5];
    const float* wk   = (const float*)d_in[6];
    const float* bk   = (const float*)d_in[7];
    const float* wv   = (const float*)d_in[8];
    const float* bv   = (const float*)d_in[9];
    const float* wo   = (const float*)d_in[10];
    const float* bo   = (const float*)d_in[11];

    float* out  = (float*)d_out;
    float* attn = out + (size_t)B_ * S_ * D_;

    float *pQh, *pKh, *pVh, *pCtx;
    cudaGetSymbolAddress((void**)&pQh,  g_Qh);
    cudaGetSymbolAddress((void**)&pKh,  g_Kh);
    cudaGetSymbolAddress((void**)&pVh,  g_Vh);
    cudaGetSymbolAddress((void**)&pCtx, g_ctx);

    gemm_tf32_kernel<true, true><<<dim3(8, 32, 3), 256>>>(
        q, wq, bq, pQh,
        k, wk, bk, pKh,
        v, wv, bv, pVh);

    static bool attr_set = false;
    if (!attr_set) {
        cudaFuncSetAttribute(attn_mma_kernel,
                             cudaFuncAttributeMaxDynamicSharedMemorySize,
                             ATTN_SMEM_BYTES);
        attr_set = true;
    }
    attn_mma_kernel<<<dim3(S_ / 64, B_ * H_), 256, ATTN_SMEM_BYTES>>>(mask, attn);

    norm_attn_kernel<<<(B_ * H_ * (size_t)S_ * S_ / 4) / 256, 256>>>(attn);

    gemm_tf32_kernel<false, false><<<dim3(8, 32, 1), 256>>>(
        pCtx, wo, bo, out,
        nullptr, nullptr, nullptr, nullptr,
        nullptr, nullptr, nullptr, nullptr);
}

// round 4
// speedup vs baseline: 3.6220x; 1.0722x over previous
#include <cuda_runtime.h>

#define B_ 2
#define S_ 2048
#define D_ 1024
#define H_ 16
#define DEPTH_ 64
#define SCALE_ 0.125f
#define NEG_ (-1.0e9f)

// Scratch (device globals — no allocations allowed)
__device__ float g_Qh[B_*H_*S_*DEPTH_];
__device__ float g_Kh[B_*H_*S_*DEPTH_];
__device__ float g_Vh[B_*H_*S_*DEPTH_];
__device__ float g_ctx[B_*S_*D_];
__device__ float g_rinv[B_*H_*S_];

__device__ __forceinline__ unsigned f2tf32(float f) {
    unsigned u; asm("cvt.rna.tf32.f32 %0, %1;" : "=r"(u) : "f"(f)); return u;
}

#define MMA_TF32(d, a, b)                                                     \
    asm volatile(                                                             \
        "mma.sync.aligned.m16n8k8.row.col.f32.tf32.tf32.f32 "                 \
        "{%0,%1,%2,%3},{%4,%5,%6,%7},{%8,%9},{%0,%1,%2,%3};"                  \
        : "+f"(d[0]), "+f"(d[1]), "+f"(d[2]), "+f"(d[3])                      \
        : "r"(a[0]), "r"(a[1]), "r"(a[2]), "r"(a[3]), "r"(b[0]), "r"(b[1]))

// ---------------------------------------------------------------------------
// tf32 tensor-core GEMM: C = A[4096,1024] @ W[1024,1024] + bias
// 128x128 CTA tile, BK=16, DOUBLE-BUFFERED smem, one barrier per K-iter.
// ---------------------------------------------------------------------------
template<bool HEADED, bool ZSEL>
__global__ __launch_bounds__(256, 2)
void gemm_tf32_kernel(const float* __restrict__ A0, const float* __restrict__ W0,
                      const float* __restrict__ bias0, float* __restrict__ C0,
                      const float* A1, const float* W1, const float* bias1, float* C1,
                      const float* A2, const float* W2, const float* bias2, float* C2)
{
    __shared__ unsigned As[2][128][20];
    __shared__ unsigned Bs[2][16][132];

    const float* A = A0; const float* W = W0; const float* bias = bias0; float* C = C0;
    if (ZSEL) {
        if (blockIdx.z == 1) { A = A1; W = W1; bias = bias1; C = C1; }
        else if (blockIdx.z == 2) { A = A2; W = W2; bias = bias2; C = C2; }
    }

    const int t    = threadIdx.x;
    const int m0   = blockIdx.y * 128;
    const int n0   = blockIdx.x * 128;
    const int lane = t & 31, warp = t >> 5;
    const int wm   = warp >> 1, wn = warp & 1;
    const int gid  = lane >> 2, tid4 = lane & 3;

    const int ar = t >> 1,  ac = (t & 1) * 8;
    const int br = t >> 4,  bc = (t & 15) * 8;

    const float* Aptr = A + (size_t)(m0 + ar) * 1024 + ac;
    const float* Wptr = W + (size_t)br * 1024 + n0 + bc;

    float acc[2][8][4];
#pragma unroll
    for (int i = 0; i < 2; i++)
#pragma unroll
        for (int j = 0; j < 8; j++)
#pragma unroll
            for (int c = 0; c < 4; c++) acc[i][j][c] = 0.f;

    // stage tile 0 and commit to buffer 0
    float4 av0 = *(const float4*)(Aptr);
    float4 av1 = *(const float4*)(Aptr + 4);
    float4 bv0 = *(const float4*)(Wptr);
    float4 bv1 = *(const float4*)(Wptr + 4);
    As[0][ar][ac + 0] = f2tf32(av0.x); As[0][ar][ac + 1] = f2tf32(av0.y);
    As[0][ar][ac + 2] = f2tf32(av0.z); As[0][ar][ac + 3] = f2tf32(av0.w);
    As[0][ar][ac + 4] = f2tf32(av1.x); As[0][ar][ac + 5] = f2tf32(av1.y);
    As[0][ar][ac + 6] = f2tf32(av1.z); As[0][ar][ac + 7] = f2tf32(av1.w);
    Bs[0][br][bc + 0] = f2tf32(bv0.x); Bs[0][br][bc + 1] = f2tf32(bv0.y);
    Bs[0][br][bc + 2] = f2tf32(bv0.z); Bs[0][br][bc + 3] = f2tf32(bv0.w);
    Bs[0][br][bc + 4] = f2tf32(bv1.x); Bs[0][br][bc + 5] = f2tf32(bv1.y);
    Bs[0][br][bc + 6] = f2tf32(bv1.z); Bs[0][br][bc + 7] = f2tf32(bv1.w);
    __syncthreads();

    for (int kt = 0; kt < 64; kt++) {
        const int cur = kt & 1, nxt = cur ^ 1;

        // issue gmem loads for next tile early (overlaps MMA below)
        if (kt < 63) {
            const int ko = (kt + 1) * 16;
            av0 = *(const float4*)(Aptr + ko);
            av1 = *(const float4*)(Aptr + ko + 4);
            bv0 = *(const float4*)(Wptr + (size_t)ko * 1024);
            bv1 = *(const float4*)(Wptr + (size_t)ko * 1024 + 4);
        }

        // MMA on current buffer
#pragma unroll
        for (int s = 0; s < 2; s++) {
            unsigned af[2][4], bf[8][2];
#pragma unroll
            for (int i = 0; i < 2; i++) {
                const int r = wm * 32 + i * 16 + gid;
                const int kc = 8 * s + tid4;
                af[i][0] = As[cur][r][kc];     af[i][1] = As[cur][r + 8][kc];
                af[i][2] = As[cur][r][kc + 4]; af[i][3] = As[cur][r + 8][kc + 4];
            }
#pragma unroll
            for (int j = 0; j < 8; j++) {
                const int cn = wn * 64 + j * 8 + gid;
                bf[j][0] = Bs[cur][8 * s + tid4][cn];
                bf[j][1] = Bs[cur][8 * s + 4 + tid4][cn];
            }
#pragma unroll
            for (int i = 0; i < 2; i++)
#pragma unroll
                for (int j = 0; j < 8; j++) MMA_TF32(acc[i][j], af[i], bf[j]);
        }

        // commit next tile into the other buffer
        if (kt < 63) {
            As[nxt][ar][ac + 0] = f2tf32(av0.x); As[nxt][ar][ac + 1] = f2tf32(av0.y);
            As[nxt][ar][ac + 2] = f2tf32(av0.z); As[nxt][ar][ac + 3] = f2tf32(av0.w);
            As[nxt][ar][ac + 4] = f2tf32(av1.x); As[nxt][ar][ac + 5] = f2tf32(av1.y);
            As[nxt][ar][ac + 6] = f2tf32(av1.z); As[nxt][ar][ac + 7] = f2tf32(av1.w);
            Bs[nxt][br][bc + 0] = f2tf32(bv0.x); Bs[nxt][br][bc + 1] = f2tf32(bv0.y);
            Bs[nxt][br][bc + 2] = f2tf32(bv0.z); Bs[nxt][br][bc + 3] = f2tf32(bv0.w);
            Bs[nxt][br][bc + 4] = f2tf32(bv1.x); Bs[nxt][br][bc + 5] = f2tf32(bv1.y);
            Bs[nxt][br][bc + 6] = f2tf32(bv1.z); Bs[nxt][br][bc + 7] = f2tf32(bv1.w);
        }
        __syncthreads();
    }

#pragma unroll
    for (int i = 0; i < 2; i++) {
#pragma unroll
        for (int j = 0; j < 8; j++) {
            const int n = n0 + wn * 64 + j * 8 + tid4 * 2;
            const float b0 = bias[n], b1 = bias[n + 1];
#pragma unroll
            for (int half = 0; half < 2; half++) {
                const int m = m0 + wm * 32 + i * 16 + gid + half * 8;
                const float v0 = acc[i][j][half * 2 + 0] + b0;
                const float v1 = acc[i][j][half * 2 + 1] + b1;
                if (HEADED) {
                    const int bb = m >> 11, s = m & 2047;
                    const int h = n >> 6, dd = n & 63;
                    float* dst = &C[(((size_t)(bb * H_ + h) << 11) + s) * DEPTH_ + dd];
                    dst[0] = v0; dst[1] = v1;
                } else {
                    C[(size_t)m * 1024 + n]     = v0;
                    C[(size_t)m * 1024 + n + 1] = v1;
                }
            }
        }
    }
}

// ---------------------------------------------------------------------------
// MMA attention, double-buffered K/V/mask, 2 barriers per tile.
// One CTA = (b,h) x 64 queries. S^T = K @ Q^T (K and V both natural [key][d]
// layout, Q^T fragments loop-invariant in registers). P roundtrips through
// smem; attn store coalesced. Single pass, no max-subtract.
// ---------------------------------------------------------------------------
#define KS(p, r, c) Ks[(p) * 4352 + (r) * 68 + (c)]
#define VS(p, r, c) Vs[(p) * 4352 + (r) * 68 + (c)]
#define PS(r, c)    Ps[(r) * 68 + (c)]
#define ATTN_SMEM_BYTES ((5 * 64 * 68 + 2 * 64 + 64) * 4)

__global__ __launch_bounds__(256, 2)
void attn_mma_kernel(const float* __restrict__ mask, float* __restrict__ attn)
{
    extern __shared__ char smem_raw[];
    unsigned* Ks = (unsigned*)smem_raw;            // [2][64][68] tf32 K
    unsigned* Vs = Ks + 2 * 4352;                  // [2][64][68] tf32 V
    float*    Ps = (float*)(Vs + 2 * 4352);        // [64][68] fp32 P [q][key]
    float*    Mt = Ps + 4352;                      // [2][64]
    float*    rowsum = Mt + 128;                   // [64]

    const int t    = threadIdx.x;
    const int bh   = blockIdx.y;
    const int b    = bh >> 4, h = bh & 15;
    const int q0   = blockIdx.x * 64;
    const int lane = t & 31, warp = t >> 5;
    const int gid  = lane >> 2, t4 = lane & 3;

    const int wmS = warp >> 2, wnS = warp & 3;   // S^T: keys x q
    const int wq  = warp >> 2, wd  = warp & 3;   // PV: q x d

    const float* __restrict__ Qbh = g_Qh + (size_t)bh * S_ * DEPTH_;
    const float* __restrict__ Kbh = g_Kh + (size_t)bh * S_ * DEPTH_;
    const float* __restrict__ Vbh = g_Vh + (size_t)bh * S_ * DEPTH_;

    // loop-invariant Q^T B-fragments
    unsigned qb[2][8][2];
#pragma unroll
    for (int j = 0; j < 2; j++) {
        const int qn = q0 + wnS * 16 + j * 8 + gid;
        const float* Qrow = Qbh + (size_t)qn * DEPTH_;
#pragma unroll
        for (int s = 0; s < 8; s++) {
            qb[j][s][0] = f2tf32(Qrow[8 * s + t4]);
            qb[j][s][1] = f2tf32(Qrow[8 * s + t4 + 4]);
        }
    }

    if (t < 64) rowsum[t] = 0.f;

    float Oa[2][2][4];
#pragma unroll
    for (int i = 0; i < 2; i++)
#pragma unroll
        for (int j = 0; j < 2; j++)
#pragma unroll
            for (int c = 0; c < 4; c++) Oa[i][j][c] = 0.f;
    float ps_part[2][2] = {{0.f, 0.f}, {0.f, 0.f}};

    // stage tile 0 and commit to buffer 0
    float4 kreg[4], vreg[4];
    float  mreg = 0.f;
#pragma unroll
    for (int r = 0; r < 4; r++) {
        const int idx = t + 256 * r, key = idx >> 4, d4 = (idx & 15) * 4;
        kreg[r] = *(const float4*)&Kbh[(size_t)key * DEPTH_ + d4];
        vreg[r] = *(const float4*)&Vbh[(size_t)key * DEPTH_ + d4];
    }
    if (t < 64) mreg = mask[b * S_ + t] * NEG_;
#pragma unroll
    for (int r = 0; r < 4; r++) {
        const int idx = t + 256 * r, key = idx >> 4, d4 = (idx & 15) * 4;
        uint4 ku, vu;
        ku.x = f2tf32(kreg[r].x); ku.y = f2tf32(kreg[r].y);
        ku.z = f2tf32(kreg[r].z); ku.w = f2tf32(kreg[r].w);
        vu.x = f2tf32(vreg[r].x); vu.y = f2tf32(vreg[r].y);
        vu.z = f2tf32(vreg[r].z); vu.w = f2tf32(vreg[r].w);
        *(uint4*)&KS(0, key, d4) = ku;
        *(uint4*)&VS(0, key, d4) = vu;
    }
    if (t < 64) Mt[t] = mreg;
    __syncthreads();

    for (int kt = 0; kt < 32; kt++) {
        const int p = kt & 1;
        const int kb = kt * 64;

        // issue gmem prefetch of next tile (overlaps S-MMA + exp)
        if (kt < 31) {
            const int kb2 = kb + 64;
#pragma unroll
            for (int r = 0; r < 4; r++) {
                const int idx = t + 256 * r, key = idx >> 4, d4 = (idx & 15) * 4;
                kreg[r] = *(const float4*)&Kbh[(size_t)(kb2 + key) * DEPTH_ + d4];
                vreg[r] = *(const float4*)&Vbh[(size_t)(kb2 + key) * DEPTH_ + d4];
            }
            if (t < 64) mreg = mask[b * S_ + kb2 + t] * NEG_;
        }

        // S^T = K @ Q^T
        float sc[2][2][4];
#pragma unroll
        for (int i = 0; i < 2; i++)
#pragma unroll
            for (int j = 0; j < 2; j++)
#pragma unroll
                for (int c = 0; c < 4; c++) sc[i][j][c] = 0.f;

#pragma unroll
        for (int s = 0; s < 8; s++) {
            unsigned af[2][4];
#pragma unroll
            for (int i = 0; i < 2; i++) {
                const int r = wmS * 32 + i * 16 + gid;
                const int kc = 8 * s + t4;
                af[i][0] = KS(p, r, kc);     af[i][1] = KS(p, r + 8, kc);
                af[i][2] = KS(p, r, kc + 4); af[i][3] = KS(p, r + 8, kc + 4);
            }
#pragma unroll
            for (int i = 0; i < 2; i++)
#pragma unroll
                for (int j = 0; j < 2; j++) MMA_TF32(sc[i][j], af[i], qb[j][s]);
        }

        // exp + scatter P^T frags into Ps[q][key]
#pragma unroll
        for (int i = 0; i < 2; i++) {
            const int kr = wmS * 32 + i * 16 + gid;
            const float m0 = Mt[p * 64 + kr], m1 = Mt[p * 64 + kr + 8];
#pragma unroll
            for (int j = 0; j < 2; j++) {
                const int qc = wnS * 16 + j * 8 + 2 * t4;
                const float p0 = __expf(sc[i][j][0] * SCALE_ + m0);
                const float p1 = __expf(sc[i][j][1] * SCALE_ + m0);
                const float p2 = __expf(sc[i][j][2] * SCALE_ + m1);
                const float p3 = __expf(sc[i][j][3] * SCALE_ + m1);
                PS(qc, kr)         = p0;
                PS(qc + 1, kr)     = p1;
                PS(qc, kr + 8)     = p2;
                PS(qc + 1, kr + 8) = p3;
                ps_part[j][0] += p0 + p2;
                ps_part[j][1] += p1 + p3;
            }
        }
        __syncthreads();   // syncA: Ps ready; prior-iter reads of buf p^1 done

        // commit next tile into other buffer (overlaps store + PV below)
        if (kt < 31) {
#pragma unroll
            for (int r = 0; r < 4; r++) {
                const int idx = t + 256 * r, key = idx >> 4, d4 = (idx & 15) * 4;
                uint4 ku, vu;
                ku.x = f2tf32(kreg[r].x); ku.y = f2tf32(kreg[r].y);
                ku.z = f2tf32(kreg[r].z); ku.w = f2tf32(kreg[r].w);
                vu.x = f2tf32(vreg[r].x); vu.y = f2tf32(vreg[r].y);
                vu.z = f2tf32(vreg[r].z); vu.w = f2tf32(vreg[r].w);
                *(uint4*)&KS(p ^ 1, key, d4) = ku;
                *(uint4*)&VS(p ^ 1, key, d4) = vu;
            }
            if (t < 64) Mt[(p ^ 1) * 64 + t] = mreg;
        }

        // coalesced store of unnormalized 64x64 P tile
#pragma unroll
        for (int r = 0; r < 4; r++) {
            const int idx = t + 256 * r, ql = idx >> 4, k4 = (idx & 15) * 4;
            const float4 pv = *(const float4*)&PS(ql, k4);
            *(float4*)&attn[((size_t)(bh * S_ + q0 + ql)) * S_ + kb + k4] = pv;
        }

        // O += P @ V
#pragma unroll
        for (int s = 0; s < 8; s++) {
            unsigned af[2][4], bf[2][2];
#pragma unroll
            for (int i = 0; i < 2; i++) {
                const int qr = wq * 32 + i * 16 + gid;
                const int kc = 8 * s + t4;
                af[i][0] = f2tf32(PS(qr, kc));     af[i][1] = f2tf32(PS(qr + 8, kc));
                af[i][2] = f2tf32(PS(qr, kc + 4)); af[i][3] = f2tf32(PS(qr + 8, kc + 4));
            }
#pragma unroll
            for (int j = 0; j < 2; j++) {
                const int dn = wd * 16 + j * 8 + gid;
                bf[j][0] = VS(p, 8 * s + t4, dn);
                bf[j][1] = VS(p, 8 * s + 4 + t4, dn);
            }
#pragma unroll
            for (int i = 0; i < 2; i++)
#pragma unroll
                for (int j = 0; j < 2; j++) MMA_TF32(Oa[i][j], af[i], bf[j]);
        }
        __syncthreads();   // syncB: buf p^1 committed; PV reads of buf p done
    }

    // rowsum reduce
#pragma unroll
    for (int j = 0; j < 2; j++)
#pragma unroll
        for (int c = 0; c < 2; c++) {
            float v = ps_part[j][c];
            v += __shfl_xor_sync(0xffffffffu, v, 4);
            v += __shfl_xor_sync(0xffffffffu, v, 8);
            v += __shfl_xor_sync(0xffffffffu, v, 16);
            ps_part[j][c] = v;
        }
    if (gid == 0) {
#pragma unroll
        for (int j = 0; j < 2; j++)
#pragma unroll
            for (int c = 0; c < 2; c++)
                atomicAdd(&rowsum[wnS * 16 + j * 8 + 2 * t4 + c], ps_part[j][c]);
    }
    __syncthreads();

    if (t < 64) g_rinv[(size_t)bh * S_ + q0 + t] = 1.0f / rowsum[t];

#pragma unroll
    for (int i = 0; i < 2; i++) {
        const int qr = wq * 32 + i * 16 + gid;
        const float r0 = 1.0f / rowsum[qr];
        const float r1 = 1.0f / rowsum[qr + 8];
#pragma unroll
        for (int j = 0; j < 2; j++) {
            const int dn = wd * 16 + j * 8 + 2 * t4;
            float* dst0 = &g_ctx[((size_t)(b * S_ + q0 + qr)) * D_ + h * DEPTH_ + dn];
            float* dst1 = &g_ctx[((size_t)(b * S_ + q0 + qr + 8)) * D_ + h * DEPTH_ + dn];
            dst0[0] = Oa[i][j][0] * r0; dst0[1] = Oa[i][j][1] * r0;
            dst1[0] = Oa[i][j][2] * r1; dst1[1] = Oa[i][j][3] * r1;
        }
    }
}

// ---------------------------------------------------------------------------
__global__ __launch_bounds__(256)
void norm_attn_kernel(float* __restrict__ attn)
{
    const size_t i = (size_t)blockIdx.x * 256 + threadIdx.x;
    float4 v = ((float4*)attn)[i];
    const float r = g_rinv[i >> 9];
    v.x *= r; v.y *= r; v.z *= r; v.w *= r;
    ((float4*)attn)[i] = v;
}

// ---------------------------------------------------------------------------
extern "C" void kernel_launch(void* const* d_in, const int* in_sizes, int n_in,
                              void* d_out, int out_size)
{
    const float* q    = (const float*)d_in[0];
    const float* k    = (const float*)d_in[1];
    const float* v    = (const float*)d_in[2];
    const float* mask = (const float*)d_in[3];
    const float* wq   = (const float*)d_in[4];
    const float* bq   = (const float*)d_in[5];
    const float* wk   = (const float*)d_in[6];
    const float* bk   = (const float*)d_in[7];
    const float* wv   = (const float*)d_in[8];
    const float* bv   = (const float*)d_in[9];
    const float* wo   = (const float*)d_in[10];
    const float* bo   = (const float*)d_in[11];

    float* out  = (float*)d_out;
    float* attn = out + (size_t)B_ * S_ * D_;

    float *pQh, *pKh, *pVh, *pCtx;
    cudaGetSymbolAddress((void**)&pQh,  g_Qh);
    cudaGetSymbolAddress((void**)&pKh,  g_Kh);
    cudaGetSymbolAddress((void**)&pVh,  g_Vh);
    cudaGetSymbolAddress((void**)&pCtx, g_ctx);

    gemm_tf32_kernel<true, true><<<dim3(8, 32, 3), 256>>>(
        q, wq, bq, pQh,
        k, wk, bk, pKh,
        v, wv, bv, pVh);

    static bool attr_set = false;
    if (!attr_set) {
        cudaFuncSetAttribute(attn_mma_kernel,
                             cudaFuncAttributeMaxDynamicSharedMemorySize,
                             ATTN_SMEM_BYTES);
        attr_set = true;
    }
    attn_mma_kernel<<<dim3(S_ / 64, B_ * H_), 256, ATTN_SMEM_BYTES>>>(mask, attn);

    norm_attn_kernel<<<(B_ * H_ * (size_t)S_ * S_ / 4) / 256, 256>>>(attn);

    gemm_tf32_kernel<false, false><<<dim3(8, 32, 1), 256>>>(
        pCtx, wo, bo, out,
        nullptr, nullptr, nullptr, nullptr,
        nullptr, nullptr, nullptr, nullptr);
}

// round 6
// speedup vs baseline: 3.9188x; 1.0819x over previous
#include <cuda_runtime.h>
#include <cstdint>

#define B_ 2
#define S_ 2048
#define D_ 1024
#define H_ 16
#define DEPTH_ 64
#define SCALE_ 0.125f
#define NEG_ (-1.0e9f)

// Scratch (device globals — no allocations allowed)
__device__ float g_Qh[B_*H_*S_*DEPTH_];
__device__ float g_Kh[B_*H_*S_*DEPTH_];
__device__ float g_Vh[B_*H_*S_*DEPTH_];
__device__ float g_ctx[B_*S_*D_];
__device__ float g_rinv[B_*H_*S_];

__device__ __forceinline__ unsigned f2tf32(float f) {
    unsigned u; asm("cvt.rna.tf32.f32 %0, %1;" : "=r"(u) : "f"(f)); return u;
}

#define MMA_TF32(d, a, b)                                                     \
    asm volatile(                                                             \
        "mma.sync.aligned.m16n8k8.row.col.f32.tf32.tf32.f32 "                 \
        "{%0,%1,%2,%3},{%4,%5,%6,%7},{%8,%9},{%0,%1,%2,%3};"                  \
        : "+f"(d[0]), "+f"(d[1]), "+f"(d[2]), "+f"(d[3])                      \
        : "r"(a[0]), "r"(a[1]), "r"(a[2]), "r"(a[3]), "r"(b[0]), "r"(b[1]))

__device__ __forceinline__ uint32_t smem_u32(const void* p) {
    uint32_t a;
    asm("{ .reg .u64 t; cvta.to.shared.u64 t, %1; cvt.u32.u64 %0, t; }"
        : "=r"(a) : "l"(p));
    return a;
}

#define CP_ASYNC16(dst, src) \
    asm volatile("cp.async.cg.shared.global [%0], [%1], 16;" :: "r"(dst), "l"(src) : "memory")
#define CP_COMMIT() asm volatile("cp.async.commit_group;" ::: "memory")
#define CP_WAIT1()  asm volatile("cp.async.wait_group 1;" ::: "memory")
#define CP_WAIT0()  asm volatile("cp.async.wait_group 0;" ::: "memory")

// ---------------------------------------------------------------------------
// tf32 tensor-core GEMM: C = A[4096,1024] @ W[1024,1024] + bias
// 128x128 CTA tile, BK=16, cp.async double-buffered staging of RAW fp32,
// tf32 conversion at fragment-load time (identical operand math).
// ---------------------------------------------------------------------------
template<bool HEADED, bool ZSEL>
__global__ __launch_bounds__(256, 2)
void gemm_tf32_kernel(const float* __restrict__ A0, const float* __restrict__ W0,
                      const float* __restrict__ bias0, float* __restrict__ C0,
                      const float* A1, const float* W1, const float* bias1, float* C1,
                      const float* A2, const float* W2, const float* bias2, float* C2)
{
    __shared__ float As[2][128][20];   // raw fp32, stride 20 (conflict-free frags)
    __shared__ float Bs[2][16][132];   // raw fp32, stride 132

    const float* A = A0; const float* W = W0; const float* bias = bias0; float* C = C0;
    if (ZSEL) {
        if (blockIdx.z == 1) { A = A1; W = W1; bias = bias1; C = C1; }
        else if (blockIdx.z == 2) { A = A2; W = W2; bias = bias2; C = C2; }
    }

    const int t    = threadIdx.x;
    const int m0   = blockIdx.y * 128;
    const int n0   = blockIdx.x * 128;
    const int lane = t & 31, warp = t >> 5;
    const int wm   = warp >> 1, wn = warp & 1;
    const int gid  = lane >> 2, tid4 = lane & 3;

    const int ar = t >> 1,  ac = (t & 1) * 8;      // A: 128 rows x 16 cols
    const int br = t >> 4,  bc = (t & 15) * 8;     // B: 16 rows x 128 cols

    const float* Aptr = A + (size_t)(m0 + ar) * 1024 + ac;
    const float* Wptr = W + (size_t)br * 1024 + n0 + bc;

    const uint32_t a_dst0 = smem_u32(&As[0][ar][ac]);
    const uint32_t a_dst1 = smem_u32(&As[1][ar][ac]);
    const uint32_t b_dst0 = smem_u32(&Bs[0][br][bc]);
    const uint32_t b_dst1 = smem_u32(&Bs[1][br][bc]);

    float acc[2][8][4];
#pragma unroll
    for (int i = 0; i < 2; i++)
#pragma unroll
        for (int j = 0; j < 8; j++)
#pragma unroll
            for (int c = 0; c < 4; c++) acc[i][j][c] = 0.f;

    // prologue: async-stage tiles 0 and 1
    {
        CP_ASYNC16(a_dst0,      Aptr);
        CP_ASYNC16(a_dst0 + 16, Aptr + 4);
        CP_ASYNC16(b_dst0,      Wptr);
        CP_ASYNC16(b_dst0 + 16, Wptr + 4);
        CP_COMMIT();
        CP_ASYNC16(a_dst1,      Aptr + 16);
        CP_ASYNC16(a_dst1 + 16, Aptr + 20);
        CP_ASYNC16(b_dst1,      Wptr + 16384);       // 16 * 1024
        CP_ASYNC16(b_dst1 + 16, Wptr + 16384 + 4);
        CP_COMMIT();
    }

    for (int kt = 0; kt < 64; kt++) {
        const int cur = kt & 1;

        if (kt >= 63) CP_WAIT0(); else CP_WAIT1();
        __syncthreads();   // stage kt visible to all

        // MMA on current buffer (cvt.rna at load — same math as pre-converted)
#pragma unroll
        for (int s = 0; s < 2; s++) {
            unsigned af[2][4], bf[8][2];
#pragma unroll
            for (int i = 0; i < 2; i++) {
                const int r = wm * 32 + i * 16 + gid;
                const int kc = 8 * s + tid4;
                af[i][0] = f2tf32(As[cur][r][kc]);
                af[i][1] = f2tf32(As[cur][r + 8][kc]);
                af[i][2] = f2tf32(As[cur][r][kc + 4]);
                af[i][3] = f2tf32(As[cur][r + 8][kc + 4]);
            }
#pragma unroll
            for (int j = 0; j < 8; j++) {
                const int cn = wn * 64 + j * 8 + gid;
                bf[j][0] = f2tf32(Bs[cur][8 * s + tid4][cn]);
                bf[j][1] = f2tf32(Bs[cur][8 * s + 4 + tid4][cn]);
            }
#pragma unroll
            for (int i = 0; i < 2; i++)
#pragma unroll
                for (int j = 0; j < 8; j++) MMA_TF32(acc[i][j], af[i], bf[j]);
        }
        __syncthreads();   // all warps done reading buf cur

        // async-stage tile kt+2 into buf cur
        if (kt + 2 < 64) {
            const int ko = (kt + 2) * 16;
            const uint32_t ad = cur ? a_dst1 : a_dst0;
            const uint32_t bd = cur ? b_dst1 : b_dst0;
            CP_ASYNC16(ad,      Aptr + ko);
            CP_ASYNC16(ad + 16, Aptr + ko + 4);
            CP_ASYNC16(bd,      Wptr + (size_t)ko * 1024);
            CP_ASYNC16(bd + 16, Wptr + (size_t)ko * 1024 + 4);
            CP_COMMIT();
        }
    }

    // epilogue: bias + store
#pragma unroll
    for (int i = 0; i < 2; i++) {
#pragma unroll
        for (int j = 0; j < 8; j++) {
            const int n = n0 + wn * 64 + j * 8 + tid4 * 2;
            const float b0 = bias[n], b1 = bias[n + 1];
#pragma unroll
            for (int half = 0; half < 2; half++) {
                const int m = m0 + wm * 32 + i * 16 + gid + half * 8;
                const float v0 = acc[i][j][half * 2 + 0] + b0;
                const float v1 = acc[i][j][half * 2 + 1] + b1;
                if (HEADED) {
                    const int bb = m >> 11, s = m & 2047;
                    const int h = n >> 6, dd = n & 63;
                    float* dst = &C[(((size_t)(bb * H_ + h) << 11) + s) * DEPTH_ + dd];
                    dst[0] = v0; dst[1] = v1;
                } else {
                    C[(size_t)m * 1024 + n]     = v0;
                    C[(size_t)m * 1024 + n + 1] = v1;
                }
            }
        }
    }
}

// ---------------------------------------------------------------------------
// MMA attention (round-4 proven version): double-buffered, S^T = K @ Q^T.
// ---------------------------------------------------------------------------
#define KS(p, r, c) Ks[(p) * 4352 + (r) * 68 + (c)]
#define VS(p, r, c) Vs[(p) * 4352 + (r) * 68 + (c)]
#define PS(r, c)    Ps[(r) * 68 + (c)]
#define ATTN_SMEM_BYTES ((5 * 64 * 68 + 2 * 64 + 64) * 4)

__global__ __launch_bounds__(256, 2)
void attn_mma_kernel(const float* __restrict__ mask, float* __restrict__ attn)
{
    extern __shared__ char smem_raw[];
    unsigned* Ks = (unsigned*)smem_raw;
    unsigned* Vs = Ks + 2 * 4352;
    float*    Ps = (float*)(Vs + 2 * 4352);
    float*    Mt = Ps + 4352;
    float*    rowsum = Mt + 128;

    const int t    = threadIdx.x;
    const int bh   = blockIdx.y;
    const int b    = bh >> 4, h = bh & 15;
    const int q0   = blockIdx.x * 64;
    const int lane = t & 31, warp = t >> 5;
    const int gid  = lane >> 2, t4 = lane & 3;

    const int wmS = warp >> 2, wnS = warp & 3;
    const int wq  = warp >> 2, wd  = warp & 3;

    const float* __restrict__ Qbh = g_Qh + (size_t)bh * S_ * DEPTH_;
    const float* __restrict__ Kbh = g_Kh + (size_t)bh * S_ * DEPTH_;
    const float* __restrict__ Vbh = g_Vh + (size_t)bh * S_ * DEPTH_;

    unsigned qb[2][8][2];
#pragma unroll
    for (int j = 0; j < 2; j++) {
        const int qn = q0 + wnS * 16 + j * 8 + gid;
        const float* Qrow = Qbh + (size_t)qn * DEPTH_;
#pragma unroll
        for (int s = 0; s < 8; s++) {
            qb[j][s][0] = f2tf32(Qrow[8 * s + t4]);
            qb[j][s][1] = f2tf32(Qrow[8 * s + t4 + 4]);
        }
    }

    if (t < 64) rowsum[t] = 0.f;

    float Oa[2][2][4];
#pragma unroll
    for (int i = 0; i < 2; i++)
#pragma unroll
        for (int j = 0; j < 2; j++)
#pragma unroll
            for (int c = 0; c < 4; c++) Oa[i][j][c] = 0.f;
    float ps_part[2][2] = {{0.f, 0.f}, {0.f, 0.f}};

    float4 kreg[4], vreg[4];
    float  mreg = 0.f;
#pragma unroll
    for (int r = 0; r < 4; r++) {
        const int idx = t + 256 * r, key = idx >> 4, d4 = (idx & 15) * 4;
        kreg[r] = *(const float4*)&Kbh[(size_t)key * DEPTH_ + d4];
        vreg[r] = *(const float4*)&Vbh[(size_t)key * DEPTH_ + d4];
    }
    if (t < 64) mreg = mask[b * S_ + t] * NEG_;
#pragma unroll
    for (int r = 0; r < 4; r++) {
        const int idx = t + 256 * r, key = idx >> 4, d4 = (idx & 15) * 4;
        uint4 ku, vu;
        ku.x = f2tf32(kreg[r].x); ku.y = f2tf32(kreg[r].y);
        ku.z = f2tf32(kreg[r].z); ku.w = f2tf32(kreg[r].w);
        vu.x = f2tf32(vreg[r].x); vu.y = f2tf32(vreg[r].y);
        vu.z = f2tf32(vreg[r].z); vu.w = f2tf32(vreg[r].w);
        *(uint4*)&KS(0, key, d4) = ku;
        *(uint4*)&VS(0, key, d4) = vu;
    }
    if (t < 64) Mt[t] = mreg;
    __syncthreads();

    for (int kt = 0; kt < 32; kt++) {
        const int p = kt & 1;
        const int kb = kt * 64;

        if (kt < 31) {
            const int kb2 = kb + 64;
#pragma unroll
            for (int r = 0; r < 4; r++) {
                const int idx = t + 256 * r, key = idx >> 4, d4 = (idx & 15) * 4;
                kreg[r] = *(const float4*)&Kbh[(size_t)(kb2 + key) * DEPTH_ + d4];
                vreg[r] = *(const float4*)&Vbh[(size_t)(kb2 + key) * DEPTH_ + d4];
            }
            if (t < 64) mreg = mask[b * S_ + kb2 + t] * NEG_;
        }

        float sc[2][2][4];
#pragma unroll
        for (int i = 0; i < 2; i++)
#pragma unroll
            for (int j = 0; j < 2; j++)
#pragma unroll
                for (int c = 0; c < 4; c++) sc[i][j][c] = 0.f;

#pragma unroll
        for (int s = 0; s < 8; s++) {
            unsigned af[2][4];
#pragma unroll
            for (int i = 0; i < 2; i++) {
                const int r = wmS * 32 + i * 16 + gid;
                const int kc = 8 * s + t4;
                af[i][0] = KS(p, r, kc);     af[i][1] = KS(p, r + 8, kc);
                af[i][2] = KS(p, r, kc + 4); af[i][3] = KS(p, r + 8, kc + 4);
            }
#pragma unroll
            for (int i = 0; i < 2; i++)
#pragma unroll
                for (int j = 0; j < 2; j++) MMA_TF32(sc[i][j], af[i], qb[j][s]);
        }

#pragma unroll
        for (int i = 0; i < 2; i++) {
            const int kr = wmS * 32 + i * 16 + gid;
            const float m0 = Mt[p * 64 + kr], m1 = Mt[p * 64 + kr + 8];
#pragma unroll
            for (int j = 0; j < 2; j++) {
                const int qc = wnS * 16 + j * 8 + 2 * t4;
                const float p0 = __expf(sc[i][j][0] * SCALE_ + m0);
                const float p1 = __expf(sc[i][j][1] * SCALE_ + m0);
                const float p2 = __expf(sc[i][j][2] * SCALE_ + m1);
                const float p3 = __expf(sc[i][j][3] * SCALE_ + m1);
                PS(qc, kr)         = p0;
                PS(qc + 1, kr)     = p1;
                PS(qc, kr + 8)     = p2;
                PS(qc + 1, kr + 8) = p3;
                ps_part[j][0] += p0 + p2;
                ps_part[j][1] += p1 + p3;
            }
        }
        __syncthreads();

        if (kt < 31) {
#pragma unroll
            for (int r = 0; r < 4; r++) {
                const int idx = t + 256 * r, key = idx >> 4, d4 = (idx & 15) * 4;
                uint4 ku, vu;
                ku.x = f2tf32(kreg[r].x); ku.y = f2tf32(kreg[r].y);
                ku.z = f2tf32(kreg[r].z); ku.w = f2tf32(kreg[r].w);
                vu.x = f2tf32(vreg[r].x); vu.y = f2tf32(vreg[r].y);
                vu.z = f2tf32(vreg[r].z); vu.w = f2tf32(vreg[r].w);
                *(uint4*)&KS(p ^ 1, key, d4) = ku;
                *(uint4*)&VS(p ^ 1, key, d4) = vu;
            }
            if (t < 64) Mt[(p ^ 1) * 64 + t] = mreg;
        }

#pragma unroll
        for (int r = 0; r < 4; r++) {
            const int idx = t + 256 * r, ql = idx >> 4, k4 = (idx & 15) * 4;
            const float4 pv = *(const float4*)&PS(ql, k4);
            *(float4*)&attn[((size_t)(bh * S_ + q0 + ql)) * S_ + kb + k4] = pv;
        }

#pragma unroll
        for (int s = 0; s < 8; s++) {
            unsigned af[2][4], bf[2][2];
#pragma unroll
            for (int i = 0; i < 2; i++) {
                const int qr = wq * 32 + i * 16 + gid;
                const int kc = 8 * s + t4;
                af[i][0] = f2tf32(PS(qr, kc));     af[i][1] = f2tf32(PS(qr + 8, kc));
                af[i][2] = f2tf32(PS(qr, kc + 4)); af[i][3] = f2tf32(PS(qr + 8, kc + 4));
            }
#pragma unroll
            for (int j = 0; j < 2; j++) {
                const int dn = wd * 16 + j * 8 + gid;
                bf[j][0] = VS(p, 8 * s + t4, dn);
                bf[j][1] = VS(p, 8 * s + 4 + t4, dn);
            }
#pragma unroll
            for (int i = 0; i < 2; i++)
#pragma unroll
                for (int j = 0; j < 2; j++) MMA_TF32(Oa[i][j], af[i], bf[j]);
        }
        __syncthreads();
    }

#pragma unroll
    for (int j = 0; j < 2; j++)
#pragma unroll
        for (int c = 0; c < 2; c++) {
            float v = ps_part[j][c];
            v += __shfl_xor_sync(0xffffffffu, v, 4);
            v += __shfl_xor_sync(0xffffffffu, v, 8);
            v += __shfl_xor_sync(0xffffffffu, v, 16);
            ps_part[j][c] = v;
        }
    if (gid == 0) {
#pragma unroll
        for (int j = 0; j < 2; j++)
#pragma unroll
            for (int c = 0; c < 2; c++)
                atomicAdd(&rowsum[wnS * 16 + j * 8 + 2 * t4 + c], ps_part[j][c]);
    }
    __syncthreads();

    if (t < 64) g_rinv[(size_t)bh * S_ + q0 + t] = 1.0f / rowsum[t];

#pragma unroll
    for (int i = 0; i < 2; i++) {
        const int qr = wq * 32 + i * 16 + gid;
        const float r0 = 1.0f / rowsum[qr];
        const float r1 = 1.0f / rowsum[qr + 8];
#pragma unroll
        for (int j = 0; j < 2; j++) {
            const int dn = wd * 16 + j * 8 + 2 * t4;
            float* dst0 = &g_ctx[((size_t)(b * S_ + q0 + qr)) * D_ + h * DEPTH_ + dn];
            float* dst1 = &g_ctx[((size_t)(b * S_ + q0 + qr + 8)) * D_ + h * DEPTH_ + dn];
            dst0[0] = Oa[i][j][0] * r0; dst0[1] = Oa[i][j][1] * r0;
            dst1[0] = Oa[i][j][2] * r1; dst1[1] = Oa[i][j][3] * r1;
        }
    }
}

// ---------------------------------------------------------------------------
__global__ __launch_bounds__(256)
void norm_attn_kernel(float* __restrict__ attn)
{
    const size_t i = (size_t)blockIdx.x * 256 + threadIdx.x;
    float4 v = ((float4*)attn)[i];
    const float r = g_rinv[i >> 9];
    v.x *= r; v.y *= r; v.z *= r; v.w *= r;
    ((float4*)attn)[i] = v;
}

// ---------------------------------------------------------------------------
extern "C" void kernel_launch(void* const* d_in, const int* in_sizes, int n_in,
                              void* d_out, int out_size)
{
    const float* q    = (const float*)d_in[0];
    const float* k    = (const float*)d_in[1];
    const float* v    = (const float*)d_in[2];
    const float* mask = (const float*)d_in[3];
    const float* wq   = (const float*)d_in[4];
    const float* bq   = (const float*)d_in[5];
    const float* wk   = (const float*)d_in[6];
    const float* bk   = (const float*)d_in[7];
    const float* wv   = (const float*)d_in[8];
    const float* bv   = (const float*)d_in[9];
    const float* wo   = (const float*)d_in[10];
    const float* bo   = (const float*)d_in[11];

    float* out  = (float*)d_out;
    float* attn = out + (size_t)B_ * S_ * D_;

    float *pQh, *pKh, *pVh, *pCtx;
    cudaGetSymbolAddress((void**)&pQh,  g_Qh);
    cudaGetSymbolAddress((void**)&pKh,  g_Kh);
    cudaGetSymbolAddress((void**)&pVh,  g_Vh);
    cudaGetSymbolAddress((void**)&pCtx, g_ctx);

    static bool attr_set = false;
    if (!attr_set) {
        cudaFuncSetAttribute(attn_mma_kernel,
                             cudaFuncAttributeMaxDynamicSharedMemorySize,
                             ATTN_SMEM_BYTES);
        attr_set = true;
    }

    gemm_tf32_kernel<true, true><<<dim3(8, 32, 3), 256>>>(
        q, wq, bq, pQh,
        k, wk, bk, pKh,
        v, wv, bv, pVh);

    attn_mma_kernel<<<dim3(S_ / 64, B_ * H_), 256, ATTN_SMEM_BYTES>>>(mask, attn);

    norm_attn_kernel<<<(B_ * H_ * (size_t)S_ * S_ / 4) / 256, 256>>>(attn);

    gemm_tf32_kernel<false, false><<<dim3(8, 32, 1), 256>>>(
        pCtx, wo, bo, out,
        nullptr, nullptr, nullptr, nullptr,
        nullptr, nullptr, nullptr, nullptr);
}